// round 4
// baseline (speedup 1.0000x reference)
#include <cuda_runtime.h>
#include <cuda_bf16.h>
#include <stdint.h>

constexpr int B    = 4;
constexpr int H    = 8;
constexpr int LQ   = 1024;
constexpr int DH   = 64;
constexpr int KLEN = 1024;
constexpr int TBL  = 33;     // 2*MAX_REL_POS + 1

// Scratch: P[b][q][j][h]  (4*1024*33*8 floats = 4.3 MB)
__device__ float Pbuf[B * LQ * TBL * H];

__device__ __forceinline__ void ffma2(unsigned long long& acc,
                                      unsigned long long a,
                                      unsigned long long b)
{
    asm("fma.rn.f32x2 %0, %1, %2, %0;" : "+l"(acc) : "l"(a), "l"(b));
}
__device__ __forceinline__ float f2lo(unsigned long long v) {
    return __uint_as_float((unsigned)v);
}
__device__ __forceinline__ float f2hi(unsigned long long v) {
    return __uint_as_float((unsigned)(v >> 32));
}

// ---------------------------------------------------------------------------
// Kernel 1: P[b,q,j,h] = dot(query[b,h,q,:], table[j,:])
// TWO threads per (b,q,h) row: thread `half` owns d in [half*32, half*32+32),
// kept in 16 packed f32x2 registers. Table rows staged in smem; each (j,c)
// read is a 2-group broadcast. Partial dots combined with one shfl_xor(.,1).
// Grid = 256 blocks -> ~3.5 warps/SMSP, half the chain latency of v1.
// ---------------------------------------------------------------------------
__global__ __launch_bounds__(256)
void proj_kernel(const float* __restrict__ q,
                 const float* __restrict__ table)
{
    __shared__ ulonglong2 tsh[TBL * 16];   // 33 rows x 64 floats (16 x ull2 each)

    const int tid = threadIdx.x;

    // stage table: 33*64 floats = 528 ulonglong2
    {
        const ulonglong2* t2 = reinterpret_cast<const ulonglong2*>(table);
        for (int i = tid; i < TBL * 16; i += 256) tsh[i] = t2[i];
    }

    const int gid  = blockIdx.x * 256 + tid;   // 0 .. 65535
    const int half = gid & 1;                  // which 32-float half of d
    const int row  = gid >> 1;                 // 0 .. 32767
    const int h    = row & 7;
    const int qpos = (row >> 3) & (LQ - 1);
    const int b    = row >> 13;

    // load this thread's 32-float half of the q row (8 x LDG.128, coalesced)
    unsigned long long qp[16];
    {
        const ulonglong2* qr = reinterpret_cast<const ulonglong2*>(
            q + ((((size_t)b * H + h) * LQ + qpos) * DH) + half * 32);
        #pragma unroll
        for (int c = 0; c < 8; c++) {
            ulonglong2 v = qr[c];
            qp[2 * c]     = v.x;
            qp[2 * c + 1] = v.y;
        }
    }
    __syncthreads();

    float* pout = Pbuf + ((size_t)b * LQ + qpos) * (TBL * H) + h;

    #pragma unroll 3
    for (int j = 0; j < TBL; j++) {
        unsigned long long a0 = 0ull, a1 = 0ull;
        const ulonglong2* tr = &tsh[j * 16 + half * 8];
        #pragma unroll
        for (int c = 0; c < 8; c++) {
            ulonglong2 t = tr[c];
            ffma2(a0, qp[2 * c],     t.x);
            ffma2(a1, qp[2 * c + 1], t.y);
        }
        float s = (f2lo(a0) + f2hi(a0)) + (f2lo(a1) + f2hi(a1));
        s += __shfl_xor_sync(0xffffffffu, s, 1);
        if (half == 0) pout[j * H] = s;
    }
}

// ---------------------------------------------------------------------------
// Kernel 2: out[b,h,q,k] = P[b,q, idx(b,q,k), h]
// One block per (b,q). idx from registers (int4 load of time_ids). P slab
// staged in smem [j][h] -> each gathered row = 2x LDS.128 (mostly broadcast,
// time ids are sorted). 8 streaming (evict-first) float4 stores per thread.
// ---------------------------------------------------------------------------
__global__ __launch_bounds__(256)
void gather_kernel(const int* __restrict__ tids,
                   float* __restrict__ out)
{
    const int blk  = blockIdx.x;        // 0 .. B*LQ-1
    const int b    = blk >> 10;
    const int qpos = blk & (LQ - 1);
    const int tid  = threadIdx.x;

    __shared__ float4 st[TBL * 2];      // P slab, [j] -> 2 float4 (8 h values)

    if (tid < TBL * 2) {
        st[tid] = reinterpret_cast<const float4*>(
            Pbuf + (size_t)blk * (TBL * H))[tid];
    }

    // idx for this thread's 4 k values, straight from registers
    const int tq = tids[b * KLEN + qpos];
    int4 t4 = reinterpret_cast<const int4*>(tids + (size_t)b * KLEN)[tid];

    int i0 = t4.x - tq; i0 = i0 < -16 ? -16 : (i0 > 16 ? 16 : i0); i0 += 16;
    int i1 = t4.y - tq; i1 = i1 < -16 ? -16 : (i1 > 16 ? 16 : i1); i1 += 16;
    int i2 = t4.z - tq; i2 = i2 < -16 ? -16 : (i2 > 16 ? 16 : i2); i2 += 16;
    int i3 = t4.w - tq; i3 = i3 < -16 ? -16 : (i3 > 16 ? 16 : i3); i3 += 16;

    __syncthreads();

    // gather 4 rows x 8 h into registers
    float r[4][8];
    {
        int ii[4] = {i0, i1, i2, i3};
        #pragma unroll
        for (int m = 0; m < 4; m++) {
            float4 a = st[2 * ii[m]];
            float4 c = st[2 * ii[m] + 1];
            r[m][0] = a.x; r[m][1] = a.y; r[m][2] = a.z; r[m][3] = a.w;
            r[m][4] = c.x; r[m][5] = c.y; r[m][6] = c.z; r[m][7] = c.w;
        }
    }

    // stream: for each h, one coalesced, evict-first float4 store
    #pragma unroll
    for (int h = 0; h < H; h++) {
        float4 v;
        v.x = r[0][h]; v.y = r[1][h]; v.z = r[2][h]; v.w = r[3][h];
        float4* o4 = reinterpret_cast<float4*>(
            out + ((((size_t)b * H + h) * LQ + qpos) * KLEN));
        __stcs(o4 + tid, v);
    }
}

extern "C" void kernel_launch(void* const* d_in, const int* in_sizes, int n_in,
                              void* d_out, int out_size)
{
    const float* q     = (const float*)d_in[0];
    const float* table = (const float*)d_in[1];
    const int*   tids  = (const int*)d_in[2];
    float*       out   = (float*)d_out;

    proj_kernel<<<(B * H * LQ * 2) / 256, 256>>>(q, table);
    gather_kernel<<<B * LQ, 256>>>(tids, out);
}